// round 13
// baseline (speedup 1.0000x reference)
#include <cuda_runtime.h>
#include <cuda_fp16.h>
#include <math.h>
#include <stdint.h>

#define Dd 1024
#define MAXN 1024
#define MAXE 32768

// ================= static scratch =================
struct Scratch {
    float X4[MAXN * 4 * Dd];      // [A | B' | C | G], ld=4096
    float biascat[4 * Dd];
    float M[Dd * Dd];
    float T1[Dd * Dd];
    float Kq[Dd * Dd];
    float W2[Dd * Dd];            // Wrr @ Wor
    float W3[Dd * Dd];            // Wrr @ Wsr
    float VWT[Dd * MAXN];         // (vf @ Wctx)^T
    float CW[MAXN * Dd];
    float GW[MAXN * Dd];
    float U1[MAXN * Dd];
    float U2[MAXN * Dd];
    float V1[MAXN * Dd];
    float V2[MAXN * Dd];
    float Pa[MAXN * MAXN];
    float Pb[MAXN * MAXN];
    float Pc[MAXN * MAXN];
    float S1[MAXN];
    float S2[MAXN];
    float quadP[(size_t)MAXE * 8];
    float logits[MAXE];
    float maxs[MAXN], sums[MAXN], maxo[MAXN], sumo[MAXN];
    float Wmat[MAXN * MAXN];
};
static __device__ Scratch g_s;

// fp16 (hi-only) operand storage
static __device__ __half g_rvfh[(size_t)MAXE * Dd];
static __device__ __half g_vfh[MAXN * Dd];
static __device__ __half g_WcatTh[4 * Dd * Dd];
static __device__ __half g_WctxTh[Dd * Dd];
static __device__ __half g_Wrrh[Dd * Dd];
static __device__ __half g_Wsrh[Dd * Dd];
static __device__ __half g_Worh[Dd * Dd];
static __device__ __half g_WorTh[Dd * Dd];
static __device__ __half g_WsrTh[Dd * Dd];
static __device__ __half g_X4h[MAXN * 4 * Dd];
static __device__ __half g_Msymh[Dd * Dd];
static __device__ __half g_T1h[Dd * Dd];
static __device__ __half g_Kqh[Dd * Dd];
static __device__ __half g_W2h[Dd * Dd];
static __device__ __half g_W3h[Dd * Dd];
static __device__ __half g_VWTh[Dd * MAXN];
static __device__ __half g_U1h[MAXN * Dd];
static __device__ __half g_U2h[MAXN * Dd];
static __device__ __half g_GWh[MAXN * Dd];
static __device__ __half g_Wmath[MAXN * MAXN];

// ================= PTX helpers =================
__device__ __forceinline__ uint32_t smem_u32(const void* p) {
    return (uint32_t)__cvta_generic_to_shared(p);
}
__device__ __forceinline__ void ldsm4(uint32_t& r0, uint32_t& r1, uint32_t& r2, uint32_t& r3, uint32_t a) {
    asm volatile("ldmatrix.sync.aligned.m8n8.x4.shared.b16 {%0,%1,%2,%3}, [%4];"
                 : "=r"(r0), "=r"(r1), "=r"(r2), "=r"(r3) : "r"(a));
}
__device__ __forceinline__ void mma_fp(float* d, const uint32_t* a, const uint32_t* b) {
    asm volatile("mma.sync.aligned.m16n8k16.row.col.f32.f16.f16.f32 "
                 "{%0,%1,%2,%3}, {%4,%5,%6,%7}, {%8,%9}, {%0,%1,%2,%3};"
                 : "+f"(d[0]), "+f"(d[1]), "+f"(d[2]), "+f"(d[3])
                 : "r"(a[0]), "r"(a[1]), "r"(a[2]), "r"(a[3]), "r"(b[0]), "r"(b[1]));
}
__device__ __forceinline__ void cpasync16(uint32_t saddr, const void* gaddr) {
    asm volatile("cp.async.cg.shared.global [%0], [%1], 16;" :: "r"(saddr), "l"(gaddr));
}
#define CP_COMMIT() asm volatile("cp.async.commit_group;" ::: "memory")
#define CP_WAIT(N)  asm volatile("cp.async.wait_group %0;" :: "n"(N) : "memory")

// ================= batched fp16 1-term mma.sync GEMM =================
// C = cscale*(Ah @ Bh^T) (+addsrc)(+bias). Both operands hi fp16.
// emit: 0 none, 1 fp16 hi, 3 final-mask mode (out = vf + involved*(acc+bias)).
// Quad mode (qp != null, B symmetric, A = xh fp16 of fp32 x at xptr):
//   quadP[m*8+blkx] = sum_n [ acc*(2x - xh) + (V1[s]+V2[o])*x ]   (= x·K·x + x·(V1+V2) to O(2^-22))
// 3-stage cp.async pipeline, ONE __syncthreads per K-chunk.
struct GemmDesc {
    const __half *Ah, *Bh;
    const float *addsrc, *bias;
    float* C;
    __half *Chi;
    const float* xptr;          // quad: rvf fp32 ; final: vf
    const int *sbjp, *objp;
    const float *v1p, *v2p;     // quad: V1,V2 ; final: sums,sumo
    float* qp;
    int lda, ldb, ldc, K, mb, nb;
    float cscale;
    int emit;
};
struct GemmBatch { GemmDesc d[6]; };

#define TILE_B    (128 * 144)              // 18432 B per matrix tile (pitch 144)
#define STAGE_B   (2 * TILE_B)             // Ah, Bh = 36864
#define SMEM_TOT  (3 * STAGE_B)            // 110592 -> 2 CTAs/SM

__global__ __launch_bounds__(256, 2)
void mgemm3(GemmBatch batch)
{
    extern __shared__ char smem[];
    const GemmDesc d = batch.d[blockIdx.z];
    if ((int)blockIdx.y >= d.mb || (int)blockIdx.x >= d.nb) return;

    const int tid = threadIdx.x;
    const int lane = tid & 31, warp = tid >> 5;
    const int wm = warp & 1, wn = warp >> 1;
    const int m0 = blockIdx.y * 128, n0 = blockIdx.x * 128;
    const int l8 = lane & 7, grp = lane >> 3;
    const int lda = d.lda, ldb = d.ldb;
    const __half *Ah = d.Ah, *Bh = d.Bh;
    const int nchunks = d.K >> 6;

    auto load_stage = [&](int stg, int chunk) {
        const uint32_t sbase = smem_u32(smem) + stg * STAGE_B;
        const int k0 = chunk << 6;
#pragma unroll
        for (int it = 0; it < 4; it++) {
            int linear = tid + it * 256;
            int row = linear >> 3, seg = (linear & 7) << 3;
            uint32_t soff = (uint32_t)(row * 144 + seg * 2);
            cpasync16(sbase + soff,          Ah + (size_t)(m0 + row) * lda + k0 + seg);
            cpasync16(sbase + TILE_B + soff, Bh + (size_t)(n0 + row) * ldb + k0 + seg);
        }
    };

    float acc[4][4][4] = {};

    load_stage(0, 0);
    CP_COMMIT();
    if (nchunks > 1) { load_stage(1, 1); CP_COMMIT(); }

    int st = 0;
    for (int i = 0; i < nchunks; i++) {
        if (i + 1 < nchunks) CP_WAIT(1); else CP_WAIT(0);
        __syncthreads();                      // ONE barrier per chunk
        if (i + 2 < nchunks) {
            int nxt = st + 2; if (nxt >= 3) nxt -= 3;
            load_stage(nxt, i + 2);           // writes stage nobody reads
            CP_COMMIT();
        }

        const char* base = smem + st * STAGE_B;
#pragma unroll
        for (int kk = 0; kk < 4; kk++) {
            const int kcol = kk * 16;
            uint32_t ah[4][4], bh[4][2];
#pragma unroll
            for (int mt = 0; mt < 4; mt++) {
                int row = wm * 64 + mt * 16 + l8 + ((grp & 1) << 3);
                int col = kcol + ((grp >> 1) << 3);
                ldsm4(ah[mt][0], ah[mt][1], ah[mt][2], ah[mt][3],
                      smem_u32(base + row * 144 + col * 2));
            }
#pragma unroll
            for (int ntp = 0; ntp < 2; ntp++) {
                int row = wn * 32 + ntp * 16 + ((grp >> 1) << 3) + l8;
                int col = kcol + ((grp & 1) << 3);
                ldsm4(bh[2 * ntp][0], bh[2 * ntp][1], bh[2 * ntp + 1][0], bh[2 * ntp + 1][1],
                      smem_u32(base + TILE_B + row * 144 + col * 2));
            }
#pragma unroll
            for (int mt = 0; mt < 4; mt++)
#pragma unroll
                for (int nt = 0; nt < 4; nt++) mma_fp(acc[mt][nt], ah[mt], bh[nt]);
        }
        if (++st == 3) st = 0;
    }

    if (d.qp) {
        // fused symmetric-quad epilogue: acc*(2x - xh) + (V1[s]+V2[o])*x
        float pt[4], pb[4];
#pragma unroll
        for (int mt = 0; mt < 4; mt++) {
            int mtop = m0 + wm * 64 + mt * 16 + (lane >> 2);
            int mbot = mtop + 8;
            int s1 = d.sbjp[mtop], o1 = d.objp[mtop];
            int s2 = d.sbjp[mbot], o2 = d.objp[mbot];
            float at = 0.f, ab = 0.f;
#pragma unroll
            for (int nt = 0; nt < 4; nt++) {
                int n = n0 + wn * 32 + nt * 8 + (lane & 3) * 2;
                float2 xt = *(const float2*)(d.xptr + (size_t)mtop * lda + n);
                float2 xb = *(const float2*)(d.xptr + (size_t)mbot * lda + n);
                float2 xht = __half22float2(*(const __half2*)(d.Ah + (size_t)mtop * lda + n));
                float2 xhb = __half22float2(*(const __half2*)(d.Ah + (size_t)mbot * lda + n));
                float2 v1t = *(const float2*)(d.v1p + (size_t)s1 * Dd + n);
                float2 v2t = *(const float2*)(d.v2p + (size_t)o1 * Dd + n);
                float2 v1b = *(const float2*)(d.v1p + (size_t)s2 * Dd + n);
                float2 v2b = *(const float2*)(d.v2p + (size_t)o2 * Dd + n);
                at += acc[mt][nt][0] * (2.f * xt.x - xht.x) + (v1t.x + v2t.x) * xt.x
                    + acc[mt][nt][1] * (2.f * xt.y - xht.y) + (v1t.y + v2t.y) * xt.y;
                ab += acc[mt][nt][2] * (2.f * xb.x - xhb.x) + (v1b.x + v2b.x) * xb.x
                    + acc[mt][nt][3] * (2.f * xb.y - xhb.y) + (v1b.y + v2b.y) * xb.y;
            }
            at += __shfl_xor_sync(0xffffffffu, at, 1);
            at += __shfl_xor_sync(0xffffffffu, at, 2);
            ab += __shfl_xor_sync(0xffffffffu, ab, 1);
            ab += __shfl_xor_sync(0xffffffffu, ab, 2);
            pt[mt] = at; pb[mt] = ab;
        }
        __syncthreads();
        float* qs = (float*)smem;
        if ((lane & 3) == 0) {
#pragma unroll
            for (int mt = 0; mt < 4; mt++) {
                int rt = wm * 64 + mt * 16 + (lane >> 2);
                qs[rt * 4 + wn] = pt[mt];
                qs[(rt + 8) * 4 + wn] = pb[mt];
            }
        }
        __syncthreads();
        if (tid < 128) {
            float q = qs[tid * 4] + qs[tid * 4 + 1] + qs[tid * 4 + 2] + qs[tid * 4 + 3];
            d.qp[(size_t)(m0 + tid) * 8 + blockIdx.x] = q;
        }
        return;
    }

    const int ldc = d.ldc;
    if (d.emit == 3) {
        // final-mask epilogue: out = vf + involved ? (acc + bias) : 0
#pragma unroll
        for (int mt = 0; mt < 4; mt++)
#pragma unroll
            for (int nt = 0; nt < 4; nt++) {
                int m = m0 + wm * 64 + mt * 16 + (lane >> 2);
                int n = n0 + wn * 32 + nt * 8 + (lane & 3) * 2;
#pragma unroll
                for (int hrow = 0; hrow < 2; hrow++) {
                    int mm = m + hrow * 8;
                    bool inv = (d.v1p[mm] > 0.f) || (d.v2p[mm] > 0.f);
                    float2 b = *(const float2*)(d.bias + n);
                    float2 base = *(const float2*)(d.xptr + (size_t)mm * ldc + n);
                    float2 v;
                    v.x = base.x + (inv ? acc[mt][nt][hrow * 2]     + b.x : 0.f);
                    v.y = base.y + (inv ? acc[mt][nt][hrow * 2 + 1] + b.y : 0.f);
                    *(float2*)(d.C + (size_t)mm * ldc + n) = v;
                }
            }
        return;
    }

    // ---- standard epilogue ----
#pragma unroll
    for (int mt = 0; mt < 4; mt++)
#pragma unroll
        for (int nt = 0; nt < 4; nt++) {
            int m = m0 + wm * 64 + mt * 16 + (lane >> 2);
            int n = n0 + wn * 32 + nt * 8 + (lane & 3) * 2;
#pragma unroll
            for (int hrow = 0; hrow < 2; hrow++) {
                int mm = m + hrow * 8;
                float2 v = make_float2(acc[mt][nt][hrow * 2] * d.cscale,
                                       acc[mt][nt][hrow * 2 + 1] * d.cscale);
                if (d.addsrc) {
                    float2 s = *(const float2*)(d.addsrc + (size_t)mm * ldc + n);
                    v.x += s.x; v.y += s.y;
                }
                if (d.bias) {
                    float2 b = *(const float2*)(d.bias + n);
                    v.x += b.x; v.y += b.y;
                }
                *(float2*)(d.C + (size_t)mm * ldc + n) = v;
                if (d.emit == 1) {
                    *(__half2*)(d.Chi + (size_t)mm * ldc + n) =
                        __halves2half2(__float2half_rn(v.x), __float2half_rn(v.y));
                }
            }
        }
}

// ================= prologue kernels =================
__global__ void rvfprep(const float4* __restrict__ src, float4* __restrict__ out,
                        __half2* __restrict__ hi, long long n4,
                        float* __restrict__ wmat, int nn2,
                        const float* __restrict__ brel, const float* __restrict__ bsbj,
                        const float* __restrict__ bobj, float* __restrict__ biascat)
{
    long long stride = (long long)gridDim.x * blockDim.x;
    long long t0 = (long long)blockIdx.x * blockDim.x + threadIdx.x;
    for (long long i = t0; i < n4; i += stride) {
        float4 v = src[i];
        out[i] = v;
        hi[2 * i]     = __halves2half2(__float2half_rn(v.x), __float2half_rn(v.y));
        hi[2 * i + 1] = __halves2half2(__float2half_rn(v.z), __float2half_rn(v.w));
    }
    for (long long i = t0; i < nn2; i += stride) wmat[i] = 0.f;
    for (long long i = t0; i < 4 * Dd; i += stride) {
        int c = (int)i >> 10, n = (int)i & 1023;
        biascat[i] = (c == 0) ? 0.f : (c == 1 ? brel[n] : (c == 2 ? bsbj[n] : bobj[n]));
    }
}

struct ToHalfDesc { const float* src; __half* hi; long long n; };
struct ToHalfBatch { ToHalfDesc d[4]; };
__global__ void tohalfmulti(ToHalfBatch b)
{
    ToHalfDesc d = b.d[blockIdx.z];
    long long n4 = d.n >> 2;
    __half2* hi2 = (__half2*)d.hi;
    const float4* s4 = (const float4*)d.src;
    for (long long i = (long long)blockIdx.x * blockDim.x + threadIdx.x; i < n4;
         i += (long long)gridDim.x * blockDim.x) {
        float4 v = s4[i];
        hi2[2 * i]     = __halves2half2(__float2half_rn(v.x), __float2half_rn(v.y));
        hi2[2 * i + 1] = __halves2half2(__float2half_rn(v.z), __float2half_rn(v.w));
    }
}

__global__ void tohalfk(const float* __restrict__ src, __half* __restrict__ hi, long long n)
{
    long long n4 = n >> 2;
    __half2* hi2 = (__half2*)hi;
    const float4* s4 = (const float4*)src;
    for (long long i = (long long)blockIdx.x * blockDim.x + threadIdx.x; i < n4;
         i += (long long)gridDim.x * blockDim.x) {
        float4 v = s4[i];
        hi2[2 * i]     = __halves2half2(__float2half_rn(v.x), __float2half_rn(v.y));
        hi2[2 * i + 1] = __halves2half2(__float2half_rn(v.z), __float2half_rn(v.w));
    }
}

struct THalfDesc { const float* src; __half* hi; int R; };
struct THalfBatch { THalfDesc d[7]; };
__global__ void thalfmulti(THalfBatch b)   // src [R][1024] -> dst [1024][R] hi
{
    THalfDesc d = b.d[blockIdx.z];
    __shared__ float tile[32][33];
    int cx = blockIdx.x * 32, ry = blockIdx.y * 32;
    if (ry >= d.R) return;
    int tx = threadIdx.x, ty = threadIdx.y;  // 32 x 8
#pragma unroll
    for (int i = 0; i < 32; i += 8)
        tile[ty + i][tx] = d.src[(size_t)(ry + ty + i) * Dd + cx + tx];
    __syncthreads();
#pragma unroll
    for (int i = 0; i < 32; i += 8) {
        float v = tile[tx][ty + i];
        d.hi[(size_t)(cx + ty + i) * d.R + ry + tx] = __float2half_rn(v);
    }
}

__global__ void msymk()   // Msym = M + M^T -> fp16 hi
{
    int idx = blockIdx.x * 256 + threadIdx.x;
    if (idx < Dd * Dd) {
        int i = idx >> 10, j = idx & 1023;
        g_Msymh[idx] = __float2half_rn(g_s.M[idx] + g_s.M[j * Dd + i]);
    }
}

// ================= graph epilogue kernels =================
__global__ void rowdots(float* __restrict__ S1, float* __restrict__ S2)
{
    int n = blockIdx.x, tid = threadIdx.x;
    const float* a  = g_s.X4 + (size_t)n * 4096;
    const float* bp = a + 1024;
    float s1 = 0.f, s2 = 0.f;
    for (int d = tid; d < Dd; d += 256) {
        s1 += a[d]  * (g_s.U1[(size_t)n * Dd + d] + g_s.CW[(size_t)n * Dd + d]);
        s2 += bp[d] * (g_s.U2[(size_t)n * Dd + d] + g_s.GW[(size_t)n * Dd + d]);
    }
    __shared__ float r1[256], r2[256];
    r1[tid] = s1; r2[tid] = s2; __syncthreads();
    for (int st = 128; st > 0; st >>= 1) {
        if (tid < st) { r1[tid] += r1[tid + st]; r2[tid] += r2[tid + st]; }
        __syncthreads();
    }
    if (tid == 0) { S1[n] = 0.5f * r1[0]; S2[n] = 0.5f * r2[0]; }
}

__global__ void logitsk(const int* __restrict__ sbj, const int* __restrict__ obj,
                        int E, int Nn, float scale)
{
    int e = blockIdx.x * 256 + threadIdx.x;
    if (e >= E) return;
    const float* qp = g_s.quadP + (size_t)e * 8;
    float q = qp[0] + qp[1] + qp[2] + qp[3] + qp[4] + qp[5] + qp[6] + qp[7];
    int s = sbj[e], o = obj[e];
    size_t po = (size_t)s * Nn + o;
    g_s.logits[e] = (q + g_s.Pa[po] + g_s.Pb[po] + g_s.Pc[po] + g_s.S1[s] + g_s.S2[o]) * scale;
}

// single-pass online-softmax segment stats for BOTH segmentations (deterministic)
__global__ void segstats(const int* __restrict__ sbj, const int* __restrict__ obj, int E)
{
    int n = blockIdx.x, tid = threadIdx.x;
    float ms = -1e30f, ss = 0.f, mo = -1e30f, so = 0.f;
    for (int e = tid; e < E; e += 256) {
        float l = g_s.logits[e];
        if (sbj[e] == n) {
            if (l > ms) { ss = ss * expf(ms - l) + 1.f; ms = l; }
            else        { ss += expf(l - ms); }
        }
        if (obj[e] == n) {
            if (l > mo) { so = so * expf(mo - l) + 1.f; mo = l; }
            else        { so += expf(l - mo); }
        }
    }
    __shared__ float rm1[256], rs1[256], rm2[256], rs2[256];
    rm1[tid] = ms; rs1[tid] = ss; rm2[tid] = mo; rs2[tid] = so;
    __syncthreads();
    for (int st = 128; st > 0; st >>= 1) {
        if (tid < st) {
            float m1 = rm1[tid], s1 = rs1[tid], m2 = rm1[tid + st], s2 = rs1[tid + st];
            float M = fmaxf(m1, m2);
            rs1[tid] = s1 * expf(m1 - M) + s2 * expf(m2 - M);
            rm1[tid] = M;
            m1 = rm2[tid]; s1 = rs2[tid]; m2 = rm2[tid + st]; s2 = rs2[tid + st];
            M = fmaxf(m1, m2);
            rs2[tid] = s1 * expf(m1 - M) + s2 * expf(m2 - M);
            rm2[tid] = M;
        }
        __syncthreads();
    }
    if (tid == 0) {
        g_s.maxs[n] = rm1[0]; g_s.sums[n] = rs1[0];
        g_s.maxo[n] = rm2[0]; g_s.sumo[n] = rs2[0];
    }
}

__global__ void wmatk(const int* __restrict__ sbj, const int* __restrict__ obj,
                      int E, int Nn)
{
    int e = blockIdx.x * 256 + threadIdx.x;
    if (e >= E) return;
    float l = g_s.logits[e];
    int s = sbj[e], o = obj[e];
    float ws = expf(l - g_s.maxs[s]) / g_s.sums[s];
    float wo = expf(l - g_s.maxo[o]) / g_s.sumo[o];
    atomicAdd(&g_s.Wmat[(size_t)s * Nn + o], ws);
    atomicAdd(&g_s.Wmat[(size_t)o * Nn + s], wo);
}

// ================= host orchestration =================
static GemmDesc mkdesc(const __half* Ah, int lda, const __half* Bh, int ldb,
                       float* C, int ldc, const float* addsrc, const float* bias,
                       __half* Chi, int M, int N, int K, float cscale = 1.0f)
{
    GemmDesc d{};
    d.Ah = Ah; d.Bh = Bh;
    d.addsrc = addsrc; d.bias = bias; d.C = C; d.Chi = Chi;
    d.lda = lda; d.ldb = ldb; d.ldc = ldc; d.K = K;
    d.mb = M / 128; d.nb = N / 128; d.cscale = cscale;
    d.emit = Chi ? 1 : 0;
    return d;
}

static void launch_batch(GemmDesc* ds, int nd)
{
    GemmBatch b{};
    int mx = 0, nx = 0;
    for (int i = 0; i < nd; i++) { b.d[i] = ds[i]; if (ds[i].mb > mx) mx = ds[i].mb; if (ds[i].nb > nx) nx = ds[i].nb; }
    for (int i = nd; i < 6; i++) { b.d[i] = ds[0]; }
    dim3 grid(nx, mx, nd);
    mgemm3<<<grid, 256, SMEM_TOT>>>(b);
}

extern "C" void kernel_launch(void* const* d_in, const int* in_sizes, int n_in,
                              void* d_out, int out_size)
{
    const float* vf   = (const float*)d_in[0];
    const float* rvf  = (const float*)d_in[1];
    const float* Wrel = (const float*)d_in[2];
    const float* brel = (const float*)d_in[3];
    const float* Wsbj = (const float*)d_in[4];
    const float* bsbj = (const float*)d_in[5];
    const float* Wobj = (const float*)d_in[6];
    const float* bobj = (const float*)d_in[7];
    const float* Wctx = (const float*)d_in[8];
    const float* bctx = (const float*)d_in[9];
    const int*   sbj  = (const int*)d_in[10];
    const int*   obj  = (const int*)d_in[11];

    const int Nn = in_sizes[0] / Dd;    // 768
    const int E  = in_sizes[10];        // 24576
    float* out = (float*)d_out;

    cudaFuncSetAttribute(mgemm3, cudaFuncAttributeMaxDynamicSharedMemorySize, SMEM_TOT);

    Scratch* S = nullptr;
    cudaGetSymbolAddress((void**)&S, g_s);
    __half *rvfh, *vfh, *WcatTh, *WctxTh, *Wrrh, *Wsrh, *Worh, *WorTh, *WsrTh;
    __half *X4h, *Msh, *T1h, *Kqh, *W2h, *W3h, *VWTh, *U1h, *U2h, *GWh, *Wmh;
    cudaGetSymbolAddress((void**)&rvfh, g_rvfh);
    cudaGetSymbolAddress((void**)&vfh, g_vfh);
    cudaGetSymbolAddress((void**)&WcatTh, g_WcatTh);
    cudaGetSymbolAddress((void**)&WctxTh, g_WctxTh);
    cudaGetSymbolAddress((void**)&Wrrh, g_Wrrh);
    cudaGetSymbolAddress((void**)&Wsrh, g_Wsrh);
    cudaGetSymbolAddress((void**)&Worh, g_Worh);
    cudaGetSymbolAddress((void**)&WorTh, g_WorTh);
    cudaGetSymbolAddress((void**)&WsrTh, g_WsrTh);
    cudaGetSymbolAddress((void**)&X4h, g_X4h);
    cudaGetSymbolAddress((void**)&Msh, g_Msymh);
    cudaGetSymbolAddress((void**)&T1h, g_T1h);
    cudaGetSymbolAddress((void**)&Kqh, g_Kqh);
    cudaGetSymbolAddress((void**)&W2h, g_W2h);
    cudaGetSymbolAddress((void**)&W3h, g_W3h);
    cudaGetSymbolAddress((void**)&VWTh, g_VWTh);
    cudaGetSymbolAddress((void**)&U1h, g_U1h);
    cudaGetSymbolAddress((void**)&U2h, g_U2h);
    cudaGetSymbolAddress((void**)&GWh, g_GWh);
    cudaGetSymbolAddress((void**)&Wmh, g_Wmath);

    const float* Wr_r = Wrel + 2 * Dd * Dd;
    const float* Ws_r = Wsbj + Dd * Dd;
    const float* Wo_r = Wobj + Dd * Dd;

    // P0: rvf copy + fp16 hi + Wmat zero + biascat
    long long n4 = (long long)E * Dd / 4;
    rvfprep<<<4096, 256>>>((const float4*)rvf, (float4*)out,
                           (__half2*)rvfh, n4,
                           S->Wmat, Nn * Nn, brel, bsbj, bobj, S->biascat);

    // P1: flat fp16 conversions (vf, Wrr, Wsr, Wor)
    {
        ToHalfBatch sb{};
        sb.d[0] = { vf,   vfh,  (long long)Nn * Dd };
        sb.d[1] = { Wr_r, Wrrh, (long long)Dd * Dd };
        sb.d[2] = { Ws_r, Wsrh, (long long)Dd * Dd };
        sb.d[3] = { Wo_r, Worh, (long long)Dd * Dd };
        tohalfmulti<<<dim3(256, 1, 4), 256>>>(sb);
    }
    // P2: transposed fp16 conversions (WctxT, WcatT x4, WorT, WsrT)
    {
        THalfBatch tb{};
        tb.d[0] = { Wctx,           WctxTh,               Dd };
        tb.d[1] = { Wrel,           WcatTh + 0 * Dd * Dd, Dd };
        tb.d[2] = { Wrel + Dd * Dd, WcatTh + 1 * Dd * Dd, Dd };
        tb.d[3] = { Wsbj,           WcatTh + 2 * Dd * Dd, Dd };
        tb.d[4] = { Wobj,           WcatTh + 3 * Dd * Dd, Dd };
        tb.d[5] = { Wo_r,           WorTh,                Dd };
        tb.d[6] = { Ws_r,           WsrTh,                Dd };
        thalfmulti<<<dim3(32, 32, 7), dim3(32, 8)>>>(tb);
    }

    // B1: X4, M, W2'=Wrr@Wor, W3'=Wrr@Wsr, VWT=Wctx^T·vf^T
    {
        GemmDesc ds[5] = {
            mkdesc(vfh, Dd, WcatTh, Dd, S->X4, 4096, nullptr, S->biascat, X4h, Nn, 4096, Dd),
            mkdesc(Wsrh, Dd, Worh, Dd, S->M, Dd, nullptr, nullptr, nullptr, Dd, Dd, Dd),
            mkdesc(Wrrh, Dd, WorTh, Dd, S->W2, Dd, nullptr, nullptr, W2h, Dd, Dd, Dd),
            mkdesc(Wrrh, Dd, WsrTh, Dd, S->W3, Dd, nullptr, nullptr, W3h, Dd, Dd, Dd),
            mkdesc(WctxTh, Dd, vfh, Dd, S->VWT, Nn, nullptr, nullptr, VWTh, Dd, Nn, Dd)
        };
        launch_batch(ds, 5);
    }
    msymk<<<(Dd * Dd + 255) / 256, 256>>>();

    // B2: T1=Wrr@Msym, CW, GW, Pa=C@G^T, V1a=C@W2'^T, V2a=G@W3'^T
    {
        GemmDesc ds[6] = {
            mkdesc(Wrrh, Dd, Msh, Dd, S->T1, Dd, nullptr, nullptr, T1h, Dd, Dd, Dd),
            mkdesc(X4h + 2048, 4096, Worh, Dd, S->CW, Dd, nullptr, nullptr, nullptr, Nn, Dd, Dd),
            mkdesc(X4h + 3072, 4096, Wsrh, Dd, S->GW, Dd, nullptr, nullptr, GWh, Nn, Dd, Dd),
            mkdesc(X4h + 2048, 4096, X4h + 3072, 4096, S->Pa, Nn, nullptr, nullptr, nullptr, Nn, Nn, Dd),
            mkdesc(X4h + 2048, 4096, W2h, Dd, S->V1, Dd, nullptr, nullptr, nullptr, Nn, Dd, Dd),
            mkdesc(X4h + 3072, 4096, W3h, Dd, S->V2, Dd, nullptr, nullptr, nullptr, Nn, Dd, Dd)
        };
        launch_batch(ds, 6);
    }

    // B3: U1=A@Msym+CW, U2=B'@Msym+GW, Kq=0.5*T1@Wrr^T, V1=A@T1^T+V1a, V2=B'@T1^T+V2a
    {
        GemmDesc ds[5] = {
            mkdesc(X4h, 4096, Msh, Dd, S->U1, Dd, S->CW, nullptr, U1h, Nn, Dd, Dd),
            mkdesc(X4h + 1024, 4096, Msh, Dd, S->U2, Dd, S->GW, nullptr, U2h, Nn, Dd, Dd),
            mkdesc(T1h, Dd, Wrrh, Dd, S->Kq, Dd, nullptr, nullptr, Kqh, Dd, Dd, Dd, 0.5f),
            mkdesc(X4h, 4096, T1h, Dd, S->V1, Dd, S->V1, nullptr, nullptr, Nn, Dd, Dd),
            mkdesc(X4h + 1024, 4096, T1h, Dd, S->V2, Dd, S->V2, nullptr, nullptr, Nn, Dd, Dd)
        };
        launch_batch(ds, 5);
    }
    rowdots<<<Nn, 256>>>(S->S1, S->S2);

    // B4: quad GEMM (xh @ Kq, symmetric-quad epilogue), Pb=U1@B'^T, Pc=A@GW^T
    {
        GemmDesc ds[3];
        ds[0] = mkdesc(rvfh, Dd, Kqh, Dd, nullptr, Dd, nullptr, nullptr,
                       nullptr, E, Dd, Dd);
        ds[0].emit = 0;
        ds[0].xptr = rvf; ds[0].sbjp = sbj; ds[0].objp = obj;
        ds[0].v1p = S->V1; ds[0].v2p = S->V2; ds[0].qp = S->quadP;
        ds[1] = mkdesc(U1h, Dd, X4h + 1024, 4096, S->Pb, Nn, nullptr, nullptr, nullptr, Nn, Nn, Dd);
        ds[2] = mkdesc(X4h, 4096, GWh, Dd, S->Pc, Nn, nullptr, nullptr, nullptr, Nn, Nn, Dd);
        launch_batch(ds, 3);
    }

    // logits, softmax stats, mixing matrix
    logitsk<<<(E + 255) / 256, 256>>>(sbj, obj, E, Nn, 1.0f / sqrtf((float)Dd));
    segstats<<<Nn, 256>>>(sbj, obj, E);
    wmatk<<<(E + 255) / 256, 256>>>(sbj, obj, E, Nn);
    tohalfk<<<256, 256>>>(S->Wmat, Wmh, (long long)Nn * Nn);

    // B5: ctxW = Wmat @ VWT^T + bctx, fused final-mask epilogue -> out
    {
        GemmDesc d = mkdesc(Wmh, Nn, VWTh, Nn, out + (size_t)E * Dd, Dd,
                            nullptr, bctx, nullptr, Nn, Dd, Nn);
        d.emit = 3;
        d.xptr = vf; d.v1p = S->sums; d.v2p = S->sumo;
        launch_batch(&d, 1);
    }
}